// round 12
// baseline (speedup 1.0000x reference)
#include <cuda_runtime.h>
#include <cuda_bf16.h>
#include <cstdint>
#include <math.h>

#define Bc    32
#define Sc    512
#define Hc    768
#define Wc    128
#define Gc    4
#define NHc   4
#define HDc   192
#define FFc   2048
#define NLc   2
#define NLABc 6
#define LW    129
#define MROWS (Bc*LW)     /* 4128 */
#define H3    (3*Hc)      /* 2304 */

// weight hi/lo pool offsets (elements)
#define OFF_QKV 0
#define SZ_QKV (NLc*H3*Hc)
#define OFF_OUT (OFF_QKV + SZ_QKV)
#define SZ_OUT (NLc*Hc*Hc)
#define OFF_FF1 (OFF_OUT + SZ_OUT)
#define SZ_FF1 (NLc*FFc*Hc)
#define OFF_FF2 (OFF_FF1 + SZ_FF1)
#define SZ_FF2 (NLc*Hc*FFc)
#define WTOT (OFF_FF2 + SZ_FF2)   /* 11,010,048 */

// ---------------- scratch (device globals; no allocation allowed) ----------
__device__ float g_x  [MROWS*Hc];
__device__ float g_qkv[MROWS*H3];
__device__ float g_y  [MROWS*Hc];
__device__ float g_wvalid[Bc*Wc];
__device__ int   g_mtype;
__device__ int   g_vtype;
__device__ __nv_bfloat16 g_wh[WTOT];
__device__ __nv_bfloat16 g_wl[WTOT];
__device__ __nv_bfloat16 g_xh[MROWS*Hc],  g_xl[MROWS*Hc];
__device__ __nv_bfloat16 g_cth[MROWS*Hc], g_ctl[MROWS*Hc];
__device__ __nv_bfloat16 g_fh[MROWS*FFc], g_fl[MROWS*FFc];

// ---------------- helpers ---------------------------------------------------
__device__ __forceinline__ uint32_t smem_u32(const void* p){
    uint32_t a;
    asm("{ .reg .u64 t; cvta.to.shared.u64 t, %1; cvt.u32.u64 %0, t; }" : "=r"(a) : "l"(p));
    return a;
}
__device__ __forceinline__ void ldsm4(uint32_t* r, uint32_t addr){
    asm volatile("ldmatrix.sync.aligned.m8n8.x4.shared.b16 {%0,%1,%2,%3}, [%4];"
        : "=r"(r[0]), "=r"(r[1]), "=r"(r[2]), "=r"(r[3]) : "r"(addr));
}
__device__ __forceinline__ void mma16816(float* c, const uint32_t* a, uint32_t b0, uint32_t b1){
    asm volatile("mma.sync.aligned.m16n8k16.row.col.f32.bf16.bf16.f32 "
        "{%0,%1,%2,%3}, {%4,%5,%6,%7}, {%8,%9}, {%0,%1,%2,%3};"
        : "+f"(c[0]), "+f"(c[1]), "+f"(c[2]), "+f"(c[3])
        : "r"(a[0]), "r"(a[1]), "r"(a[2]), "r"(a[3]), "r"(b0), "r"(b1));
}
__device__ __forceinline__ void split1(float v, __nv_bfloat16* hp, __nv_bfloat16* lp){
    __nv_bfloat16 h = __float2bfloat16(v);
    *hp = h;
    *lp = __float2bfloat16(v - __bfloat162float(h));
}
__device__ __forceinline__ void split2(float2 v, __nv_bfloat16* hp, __nv_bfloat16* lp){
    __nv_bfloat162 h = __floats2bfloat162_rn(v.x, v.y);
    __nv_bfloat162 l = __floats2bfloat162_rn(v.x - __bfloat162float(h.x),
                                             v.y - __bfloat162float(h.y));
    *(__nv_bfloat162*)hp = h;
    *(__nv_bfloat162*)lp = l;
}
__device__ __forceinline__ void cpa16(uint32_t dst, const void* src, int szbytes){
    asm volatile("cp.async.cg.shared.global [%0], [%1], 16, %2;"
        :: "r"(dst), "l"(src), "r"(szbytes) : "memory");
}
#define CP_COMMIT() asm volatile("cp.async.commit_group;" ::: "memory")
#define CP_WAIT2()  asm volatile("cp.async.wait_group 2;" ::: "memory")

// ---------------- merged weight conversion fp32 -> hi/lo bf16 ---------------
__global__ void wconv_all_kernel(const float* __restrict__ qkv_w,
                                 const float* __restrict__ out_w,
                                 const float* __restrict__ ff1_w,
                                 const float* __restrict__ ff2_w,
                                 __nv_bfloat16* __restrict__ hi,
                                 __nv_bfloat16* __restrict__ lo){
    int i = (blockIdx.x * 256 + threadIdx.x) << 2;
    if (i >= WTOT) return;
    const float* src;
    int off;
    if      (i < OFF_OUT) { src = qkv_w; off = i - OFF_QKV; }
    else if (i < OFF_FF1) { src = out_w; off = i - OFF_OUT; }
    else if (i < OFF_FF2) { src = ff1_w; off = i - OFF_FF1; }
    else                  { src = ff2_w; off = i - OFF_FF2; }
    float4 v = *(const float4*)(src + off);
    __nv_bfloat162 h0 = __floats2bfloat162_rn(v.x, v.y);
    __nv_bfloat162 h1 = __floats2bfloat162_rn(v.z, v.w);
    __nv_bfloat162 l0 = __floats2bfloat162_rn(v.x - __bfloat162float(h0.x),
                                              v.y - __bfloat162float(h0.y));
    __nv_bfloat162 l1 = __floats2bfloat162_rn(v.z - __bfloat162float(h1.x),
                                              v.w - __bfloat162float(h1.y));
    *(uint2*)(hi + i) = make_uint2(*(uint32_t*)&h0, *(uint32_t*)&h1);
    *(uint2*)(lo + i) = make_uint2(*(uint32_t*)&l0, *(uint32_t*)&l1);
}

// ---------------- dtype detection for bool inputs --------------------------
__global__ void detect_kernel(const unsigned int* __restrict__ gm,
                              const unsigned int* __restrict__ wv) {
    __shared__ int fm, bm_, fv, bv;
    int tid = threadIdx.x;
    if (tid == 0) { fm = 0; bm_ = 0; fv = 0; bv = 0; }
    __syncthreads();
    for (int i = tid; i < 4096; i += 256) {
        unsigned v = gm[i];
        if (v == 0x3f800000u) atomicOr(&fm, 1);
        else if (v > 1u)      atomicOr(&bm_, 1);
    }
    for (int i = tid; i < 1024; i += 256) {
        unsigned v = wv[i];
        if (v == 0x3f800000u) atomicOr(&fv, 1);
        else if (v > 1u)      atomicOr(&bv, 1);
    }
    __syncthreads();
    if (tid == 0) {
        g_mtype = fm ? 0 : (bm_ ? 1 : 2);
        g_vtype = fv ? 0 : (bv ? 1 : 2);
    }
}

__device__ __forceinline__ float read_flag(const void* p, int t, int i) {
    if (t == 0) return ((const float*)p)[i];
    if (t == 1) return (float)((const unsigned char*)p)[i];
    return (float)((const int*)p)[i];
}

// ---------------- build x = [cls ; word embeddings] + hi/lo -----------------
__global__ void build_kernel(const float* __restrict__ hidden,
                             const int*   __restrict__ widx,
                             const void*  __restrict__ gmask,
                             const void*  __restrict__ wvin,
                             float* __restrict__ x,
                             __nv_bfloat16* __restrict__ xh,
                             __nv_bfloat16* __restrict__ xl,
                             float* __restrict__ wvalid) {
    int qi  = blockIdx.x;
    int b   = blockIdx.y;
    int tid = threadIdx.x;
    size_t ro = ((size_t)(b*LW) + qi) * Hc;
    float* xr = x + ro;
    if (qi == 0) {
        const float* hr = hidden + (size_t)b * Sc * Hc;
        #pragma unroll
        for (int u = 0; u < 3; u++) {
            float v = hr[tid + 256*u];
            xr[tid + 256*u] = v;
            split1(v, xh + ro + tid + 256*u, xl + ro + tid + 256*u);
        }
        return;
    }
    int w = qi - 1;
    int mt = g_mtype, vt = g_vtype;
    int base = (b*Wc + w) * Gc;
    float mk0 = read_flag(gmask, mt, base+0);
    float mk1 = read_flag(gmask, mt, base+1);
    float mk2 = read_flag(gmask, mt, base+2);
    float mk3 = read_flag(gmask, mt, base+3);
    float cnt = mk0 + mk1 + mk2 + mk3;
    float valid = read_flag(wvin, vt, b*Wc + w);
    if (tid == 0) wvalid[b*Wc + w] = valid;
    float invc = valid / fmaxf(cnt, 1.f);
    const float* hb = hidden + (size_t)b * Sc * Hc;
    const float* r0 = hb + (size_t)widx[base+0] * Hc;
    const float* r1 = hb + (size_t)widx[base+1] * Hc;
    const float* r2 = hb + (size_t)widx[base+2] * Hc;
    const float* r3 = hb + (size_t)widx[base+3] * Hc;
    for (int d = tid; d < Hc; d += 256) {
        float acc = (mk0*r0[d] + mk1*r1[d] + mk2*r2[d] + mk3*r3[d]) * invc;
        xr[d] = acc;
        split1(acc, xh + ro + d, xl + ro + d);
    }
}

// ---------------- split-bf16 mma.sync GEMM (3-stage cp.async, occ 1) --------
// C[M,N] = (Ah+Al)[M,K] @ (Bh+Bl)[N,K]^T + bias (+res / relu)
// acc += Ah*Bh + Ah*Bl + Al*Bh. CTA 128x128, BK=32, 8 warps (4m x 2n).
// All fragments preloaded per k16; MMAs issued term-major so dependent MMAs
// on the same accumulator are 16 issue slots apart (no RAW scoreboard stall).
#define ROWB 80
#define MATB (128*ROWB)          /* 10240 B per matrix-half */
#define STAGEB (4*MATB)          /* 40960: Ah,Al,Bh,Bl */
#define NSTAGE 3
#define GEMM_SMEM (NSTAGE*STAGEB)  /* 122880 */

template<int EPI>  // 0=bias->f32, 1=bias+relu->hi/lo, 2=bias+res->f32
__global__ __launch_bounds__(256, 1) void hgemm_kernel(
        const __nv_bfloat16* __restrict__ Ah, const __nv_bfloat16* __restrict__ Al,
        const __nv_bfloat16* __restrict__ Bh, const __nv_bfloat16* __restrict__ Bl,
        const float* __restrict__ bias, const float* __restrict__ res,
        float* __restrict__ C,
        __nv_bfloat16* __restrict__ Ch, __nv_bfloat16* __restrict__ Cl,
        int M_, int N_, int K_) {
    extern __shared__ char smc[];
    const uint32_t sb = smem_u32(smc);
    const int tid = threadIdx.x, wid = tid >> 5, lane = tid & 31;
    const int bm = blockIdx.y * 128, bn = blockIdx.x * 128;
    const int wm = (wid & 3) * 32, wn = (wid >> 2) * 64;

    const int r  = tid >> 1;
    const int cb = (tid & 1) << 4;   // 16 bf16 = 32B = 2x 16B chunks
    const bool aok = (bm + r) < M_;
    const int asz = aok ? 16 : 0;
    const int arow = aok ? (bm + r) : (M_ - 1);   // clamp (size 0 -> no read)
    const __nv_bfloat16* Ahp = Ah + (size_t)arow * K_ + cb;
    const __nv_bfloat16* Alp = Al + (size_t)arow * K_ + cb;
    const __nv_bfloat16* Bhp = Bh + (size_t)(bn + r) * K_ + cb;
    const __nv_bfloat16* Blp = Bl + (size_t)(bn + r) * K_ + cb;
    const uint32_t so = (uint32_t)r * ROWB + (uint32_t)cb * 2u;
    const int KT = K_ >> 5;          // >= 24 for all shapes here

#define ISSUE(kt, st, bsz) do { \
    uint32_t _d = sb + (uint32_t)(st)*STAGEB + so; \
    const __nv_bfloat16* _a  = Ahp + (size_t)(kt)*32; \
    const __nv_bfloat16* _al = Alp + (size_t)(kt)*32; \
    const __nv_bfloat16* _b  = Bhp + (size_t)(kt)*32; \
    const __nv_bfloat16* _bl = Blp + (size_t)(kt)*32; \
    int _as = (bsz) ? asz : 0; \
    cpa16(_d,               _a,      _as); \
    cpa16(_d + 16,          _a  + 8, _as); \
    cpa16(_d +   MATB,      _al,     _as); \
    cpa16(_d +   MATB + 16, _al + 8, _as); \
    cpa16(_d + 2*MATB,      _b,      (bsz)); \
    cpa16(_d + 2*MATB + 16, _b  + 8, (bsz)); \
    cpa16(_d + 3*MATB,      _bl,     (bsz)); \
    cpa16(_d + 3*MATB + 16, _bl + 8, (bsz)); \
    } while(0)

    float acc[2][8][4];
    #pragma unroll
    for (int i = 0; i < 2; i++)
        #pragma unroll
        for (int j = 0; j < 8; j++)
            #pragma unroll
            for (int q = 0; q < 4; q++) acc[i][j][q] = 0.f;

    const uint32_t aoff = (uint32_t)(lane & 15) * ROWB + (uint32_t)(lane >> 4) * 16u;

    ISSUE(0, 0, 16); CP_COMMIT();
    ISSUE(1, 1, 16); CP_COMMIT();
    ISSUE(2, 2, 16); CP_COMMIT();
    CP_WAIT2();
    __syncthreads();               // stage 0 ready

    int cur = 0;
    for (int kt = 0; kt < KT; kt++) {
        const uint32_t SA = sb + (uint32_t)cur * STAGEB;
        const uint32_t SAh = SA, SAl = SA + MATB, SBh = SA + 2*MATB, SBl = SA + 3*MATB;
        #pragma unroll
        for (int k16 = 0; k16 < 32; k16 += 16) {
            uint32_t ah[2][4], al[2][4], bh[4][4], bl[4][4];
            ldsm4(ah[0], SAh + (uint32_t)(wm     )*ROWB + aoff + k16*2u);
            ldsm4(ah[1], SAh + (uint32_t)(wm + 16)*ROWB + aoff + k16*2u);
            ldsm4(al[0], SAl + (uint32_t)(wm     )*ROWB + aoff + k16*2u);
            ldsm4(al[1], SAl + (uint32_t)(wm + 16)*ROWB + aoff + k16*2u);
            #pragma unroll
            for (int nf = 0; nf < 4; nf++) {
                ldsm4(bh[nf], SBh + (uint32_t)(wn + nf*16)*ROWB + aoff + k16*2u);
                ldsm4(bl[nf], SBl + (uint32_t)(wn + nf*16)*ROWB + aoff + k16*2u);
            }
            // term-major: 16 independent MMAs per pass
            #pragma unroll
            for (int nf = 0; nf < 4; nf++)
                #pragma unroll
                for (int mf = 0; mf < 2; mf++) {
                    mma16816(acc[mf][nf*2+0], ah[mf], bh[nf][0], bh[nf][2]);
                    mma16816(acc[mf][nf*2+1], ah[mf], bh[nf][1], bh[nf][3]);
                }
            #pragma unroll
            for (int nf = 0; nf < 4; nf++)
                #pragma unroll
                for (int mf = 0; mf < 2; mf++) {
                    mma16816(acc[mf][nf*2+0], ah[mf], bl[nf][0], bl[nf][2]);
                    mma16816(acc[mf][nf*2+1], ah[mf], bl[nf][1], bl[nf][3]);
                }
            #pragma unroll
            for (int nf = 0; nf < 4; nf++)
                #pragma unroll
                for (int mf = 0; mf < 2; mf++) {
                    mma16816(acc[mf][nf*2+0], al[mf], bh[nf][0], bh[nf][2]);
                    mma16816(acc[mf][nf*2+1], al[mf], bh[nf][1], bh[nf][3]);
                }
        }
        __syncthreads();           // all warps done reading stage cur
        {
            const int nk = kt + NSTAGE;
            const int ktc = (nk < KT) ? nk : (KT - 1);   // clamped address
            const int bsz = (nk < KT) ? 16 : 0;          // zero-fill beyond
            ISSUE(ktc, cur, bsz);
            CP_COMMIT();
        }
        CP_WAIT2();
        __syncthreads();           // next stage ready
        cur = (cur + 1 == NSTAGE) ? 0 : cur + 1;
    }

    // epilogue
    #pragma unroll
    for (int mf = 0; mf < 2; mf++) {
        #pragma unroll
        for (int nf = 0; nf < 8; nf++) {
            const int row0 = bm + wm + mf*16 + (lane >> 2);
            const int col  = bn + wn + nf*8 + ((lane & 3) << 1);
            float2 b2 = *(const float2*)(bias + col);
            #pragma unroll
            for (int half = 0; half < 2; half++) {
                const int rw = row0 + half*8;
                if (rw >= M_) continue;
                float2 v = make_float2(acc[mf][nf][half*2+0] + b2.x,
                                       acc[mf][nf][half*2+1] + b2.y);
                const size_t o = (size_t)rw * N_ + col;
                if (EPI == 2) {
                    float2 rr = *(const float2*)(res + o);
                    v.x += rr.x; v.y += rr.y;
                }
                if (EPI == 1) {
                    v.x = fmaxf(v.x, 0.f); v.y = fmaxf(v.y, 0.f);
                    split2(v, Ch + o, Cl + o);
                } else {
                    *(float2*)(C + o) = v;
                }
            }
        }
    }
#undef ISSUE
}

// ---------------- attention: one block per (b, h) ---------------------------
#define PADK 196
#define PADL 132
#define ATTN_SMEM ((LW*PADK + HDc*PADL + 8*768 + 132) * 4)

__global__ __launch_bounds__(256, 1) void attn_kernel(
        const float* __restrict__ qkv,
        const float* __restrict__ wvalid,
        __nv_bfloat16* __restrict__ cth,
        __nv_bfloat16* __restrict__ ctl) {
    const int h = blockIdx.x, b = blockIdx.y;
    extern __shared__ float sm[];
    float* Ks   = sm;                    // [LW][196]
    float* Vt   = Ks + LW * PADK;        // [192][132] transposed
    float* sq   = Vt + HDc * PADL;       // 8 warps x 768
    float* madd = sq + 8 * 768;          // 132
    const int tid = threadIdx.x, w = tid >> 5, lane = tid & 31;

    const float* base = qkv + (size_t)(b * LW) * H3 + h * HDc;
    for (int idx = tid; idx < LW * HDc; idx += 256) {
        int rr = idx / HDc, c = idx - rr * HDc;
        Ks[rr * PADK + c] = base[(size_t)rr * H3 + Hc + c];
        Vt[c * PADL + rr] = base[(size_t)rr * H3 + 2*Hc + c];
    }
    if (tid < HDc) {
        Vt[tid * PADL + 129] = 0.f;
        Vt[tid * PADL + 130] = 0.f;
        Vt[tid * PADL + 131] = 0.f;
    }
    for (int kk = tid; kk < LW; kk += 256)
        madd[kk] = (kk == 0 || wvalid[b * Wc + kk - 1] > 0.5f) ? 0.f : -3.0e38f;
    __syncthreads();

    const float scale = 0.07216878364870323f; // 1/sqrt(192)
    float* myq = sq + w * 768;

    for (int q0 = w * 4; q0 < LW; q0 += 32) {
        const int nq = (LW - q0 < 4) ? (LW - q0) : 4;
        #pragma unroll
        for (int t = 0; t < 4; t++) {
            if (t < nq) {
                const float* qr = qkv + (size_t)(b * LW + q0 + t) * H3 + h * HDc;
                for (int j = lane; j < 48; j += 32)
                    *(float4*)&myq[t*192 + j*4] = *(const float4*)&qr[j*4];
            } else {
                for (int j = lane; j < 48; j += 32)
                    *(float4*)&myq[t*192 + j*4] = make_float4(0.f,0.f,0.f,0.f);
            }
        }
        __syncwarp();

        float s[4][4];
        #pragma unroll
        for (int t = 0; t < 4; t++)
            #pragma unroll
            for (int i = 0; i < 4; i++) s[t][i] = 0.f;

        #pragma unroll 2
        for (int d4 = 0; d4 < HDc; d4 += 4) {
            float4 qv[4];
            qv[0] = *(const float4*)&myq[0*192 + d4];
            qv[1] = *(const float4*)&myq[1*192 + d4];
            qv[2] = *(const float4*)&myq[2*192 + d4];
            qv[3] = *(const float4*)&myq[3*192 + d4];
            float4 kv[4];
            kv[0] = *(const float4*)&Ks[(lane      ) * PADK + d4];
            kv[1] = *(const float4*)&Ks[(lane + 32 ) * PADK + d4];
            kv[2] = *(const float4*)&Ks[(lane + 64 ) * PADK + d4];
            kv[3] = *(const float4*)&Ks[(lane + 96 ) * PADK + d4];
            #pragma unroll
            for (int t = 0; t < 4; t++)
                #pragma unroll
                for (int i = 0; i < 4; i++)
                    s[t][i] += qv[t].x*kv[i].x + qv[t].y*kv[i].y
                             + qv[t].z*kv[i].z + qv[t].w*kv[i].w;
        }

        float s128[4];
        #pragma unroll
        for (int t = 0; t < 4; t++) {
            float p = 0.f;
            #pragma unroll
            for (int j = 0; j < 6; j++)
                p += myq[t*192 + lane + 32*j] * Ks[128 * PADK + lane + 32*j];
            #pragma unroll
            for (int o = 16; o > 0; o >>= 1) p += __shfl_xor_sync(0xffffffffu, p, o);
            s128[t] = p;
        }

        const float m0 = madd[lane], m1 = madd[lane+32], m2 = madd[lane+64], m3 = madd[lane+96];
        const float m128 = madd[128];
        float e[4][4], e128[4], inv[4];
        #pragma unroll
        for (int t = 0; t < 4; t++) {
            s[t][0] = s[t][0]*scale + m0;
            s[t][1] = s[t][1]*scale + m1;
            s[t][2] = s[t][2]*scale + m2;
            s[t][3] = s[t][3]*scale + m3;
            s128[t] = s128[t]*scale + m128;
            float mm = fmaxf(fmaxf(s[t][0], s[t][1]), fmaxf(s[t][2], s[t][3]));
            #pragma unroll
            for (int o = 16; o > 0; o >>= 1) mm = fmaxf(mm, __shfl_xor_sync(0xffffffffu, mm, o));
            mm = fmaxf(mm, s128[t]);
            e[t][0] = expf(s[t][0] - mm); e[t][1] = expf(s[t][1] - mm);
            e[t][2] = expf(s[t][2] - mm); e[t][3] = expf(s[t][3] - mm);
            float ss = e[t][0] + e[t][1] + e[t][2] + e[t][3];
            #pragma unroll
            for (int o = 16; o > 0; o >>= 1) ss += __shfl_xor_sync(0xffffffffu, ss, o);
            e128[t] = expf(s128[t] - mm);
            ss += e128[t];
            inv[t] = 1.f / ss;
        }
        __syncwarp();
        #pragma unroll
        for (int t = 0; t < 4; t++) {
            myq[t*192 + lane     ] = e[t][0];
            myq[t*192 + lane + 32] = e[t][1];
            myq[t*192 + lane + 64] = e[t][2];
            myq[t*192 + lane + 96] = e[t][3];
            if (lane == 0) myq[t*192 + 128] = e128[t];
            if (lane >= 1 && lane <= 3) myq[t*192 + 128 + lane] = 0.f;
        }
        __syncwarp();

        // AV: acc[t][j] over d = lane+32j, float4 across keys
        float acc[4][6];
        #pragma unroll
        for (int t = 0; t < 4; t++)
            #pragma unroll
            for (int j = 0; j < 6; j++) acc[t][j] = 0.f;
        #pragma unroll 2
        for (int kk4 = 0; kk4 < 132; kk4 += 4) {
            float4 p0 = *(const float4*)&myq[0*192 + kk4];
            float4 p1 = *(const float4*)&myq[1*192 + kk4];
            float4 p2 = *(const float4*)&myq[2*192 + kk4];
            float4 p3 = *(const float4*)&myq[3*192 + kk4];
            #pragma unroll
            for (int j = 0; j < 6; j++) {
                float4 v = *(const float4*)&Vt[(lane + 32*j) * PADL + kk4];
                acc[0][j] += p0.x*v.x + p0.y*v.y + p0.z*v.z + p0.w*v.w;
                acc[1][j] += p1.x*v.x + p1.y*v.y + p1.z*v.z + p1.w*v.w;
                acc[2][j] += p2.x*v.x + p2.y*v.y + p2.z*v.z + p2.w*v.w;
                acc[3][j] += p3.x*v.x + p3.y*v.y + p3.z*v.z + p3.w*v.w;
            }
        }
        for (int t = 0; t < nq; t++) {
            size_t ro = (size_t)(b * LW + q0 + t) * Hc + h * HDc;
            #pragma unroll
            for (int j = 0; j < 6; j++) {
                float val = acc[t][j] * inv[t];
                split1(val, cth + ro + lane + 32*j, ctl + ro + lane + 32*j);
            }
        }
        __syncwarp();
    }
}

// ---------------- layernorm over H=768 per row + hi/lo ----------------------
__global__ void ln_kernel(const float* __restrict__ y,
                          const float* __restrict__ s,
                          const float* __restrict__ bi,
                          float* __restrict__ x,
                          __nv_bfloat16* __restrict__ xh,
                          __nv_bfloat16* __restrict__ xl) {
    int row = blockIdx.x;
    int tid = threadIdx.x;
    __shared__ float red[256];
    const float* yr = y + (size_t)row * Hc;
    float v0 = yr[tid], v1 = yr[tid+256], v2 = yr[tid+512];
    red[tid] = v0 + v1 + v2; __syncthreads();
    for (int o = 128; o > 0; o >>= 1) { if (tid < o) red[tid] += red[tid+o]; __syncthreads(); }
    float mean = red[0] * (1.f/768.f);
    __syncthreads();
    float d0 = v0-mean, d1 = v1-mean, d2 = v2-mean;
    red[tid] = d0*d0 + d1*d1 + d2*d2; __syncthreads();
    for (int o = 128; o > 0; o >>= 1) { if (tid < o) red[tid] += red[tid+o]; __syncthreads(); }
    float inv = rsqrtf(red[0] * (1.f/768.f) + 1e-5f);
    size_t ro = (size_t)row * Hc;
    float o0 = d0*inv*s[tid]     + bi[tid];
    float o1 = d1*inv*s[tid+256] + bi[tid+256];
    float o2 = d2*inv*s[tid+512] + bi[tid+512];
    x[ro+tid] = o0; x[ro+tid+256] = o1; x[ro+tid+512] = o2;
    split1(o0, xh + ro + tid,     xl + ro + tid);
    split1(o1, xh + ro + tid+256, xl + ro + tid+256);
    split1(o2, xh + ro + tid+512, xl + ro + tid+512);
}

// ---------------- classifier + pooled copy ----------------------------------
__global__ void cls_kernel(const float* __restrict__ x,
                           const float* __restrict__ cw,
                           const float* __restrict__ cb,
                           float* __restrict__ out) {
    int b = blockIdx.x;
    int tid = threadIdx.x;
    __shared__ float red[256];
    const float* row = x + (size_t)(b*LW) * Hc;
    out[Bc*NLABc + b*Hc + tid]     = row[tid];
    out[Bc*NLABc + b*Hc + tid+256] = row[tid+256];
    out[Bc*NLABc + b*Hc + tid+512] = row[tid+512];
    for (int lab = 0; lab < NLABc; lab++) {
        const float* wr = cw + lab*Hc;
        float s = row[tid]*wr[tid] + row[tid+256]*wr[tid+256] + row[tid+512]*wr[tid+512];
        red[tid] = s; __syncthreads();
        for (int o = 128; o > 0; o >>= 1) { if (tid < o) red[tid] += red[tid+o]; __syncthreads(); }
        if (tid == 0) out[b*NLABc + lab] = red[0] + cb[lab];
        __syncthreads();
    }
}

// ---------------- launch -----------------------------------------------------
extern "C" void kernel_launch(void* const* d_in, const int* in_sizes, int n_in,
                              void* d_out, int out_size) {
    (void)in_sizes; (void)n_in; (void)out_size;
    const float* hidden = (const float*)d_in[0];
    const int*   widx   = (const int*)  d_in[1];
    const void*  gmask  = d_in[2];
    const void*  wvin   = d_in[3];
    const float* qkv_w  = (const float*)d_in[4];
    const float* qkv_b  = (const float*)d_in[5];
    const float* out_w  = (const float*)d_in[6];
    const float* out_b  = (const float*)d_in[7];
    const float* ff1_w  = (const float*)d_in[8];
    const float* ff1_b  = (const float*)d_in[9];
    const float* ff2_w  = (const float*)d_in[10];
    const float* ff2_b  = (const float*)d_in[11];
    const float* ln1_s  = (const float*)d_in[12];
    const float* ln1_b  = (const float*)d_in[13];
    const float* ln2_s  = (const float*)d_in[14];
    const float* ln2_b  = (const float*)d_in[15];
    const float* cls_w  = (const float*)d_in[16];
    const float* cls_b  = (const float*)d_in[17];
    float* out = (float*)d_out;

    float *x, *qkv, *y, *wval;
    __nv_bfloat16 *wh, *wl, *xh, *xl, *cth, *ctl, *fh, *fl;
    cudaGetSymbolAddress((void**)&x,    g_x);
    cudaGetSymbolAddress((void**)&qkv,  g_qkv);
    cudaGetSymbolAddress((void**)&y,    g_y);
    cudaGetSymbolAddress((void**)&wval, g_wvalid);
    cudaGetSymbolAddress((void**)&wh,   g_wh);
    cudaGetSymbolAddress((void**)&wl,   g_wl);
    cudaGetSymbolAddress((void**)&xh,   g_xh);
    cudaGetSymbolAddress((void**)&xl,   g_xl);
    cudaGetSymbolAddress((void**)&cth,  g_cth);
    cudaGetSymbolAddress((void**)&ctl,  g_ctl);
    cudaGetSymbolAddress((void**)&fh,   g_fh);
    cudaGetSymbolAddress((void**)&fl,   g_fl);

    cudaFuncSetAttribute(hgemm_kernel<0>, cudaFuncAttributeMaxDynamicSharedMemorySize, (int)GEMM_SMEM);
    cudaFuncSetAttribute(hgemm_kernel<1>, cudaFuncAttributeMaxDynamicSharedMemorySize, (int)GEMM_SMEM);
    cudaFuncSetAttribute(hgemm_kernel<2>, cudaFuncAttributeMaxDynamicSharedMemorySize, (int)GEMM_SMEM);
    cudaFuncSetAttribute(attn_kernel,     cudaFuncAttributeMaxDynamicSharedMemorySize, (int)ATTN_SMEM);

    // weight conversion (once per launch, single merged launch)
    wconv_all_kernel<<<(WTOT/4 + 255)/256, 256>>>(qkv_w, out_w, ff1_w, ff2_w, wh, wl);

    detect_kernel<<<1, 256>>>((const unsigned int*)gmask, (const unsigned int*)wvin);
    build_kernel<<<dim3(LW, Bc), 256>>>(hidden, widx, gmask, wvin, x, xh, xl, wval);

    const int MB = (MROWS + 127) / 128;  // 33
    for (int l = 0; l < NLc; l++) {
        hgemm_kernel<0><<<dim3(H3/128, MB), 256, GEMM_SMEM>>>(
            xh, xl, wh + OFF_QKV + (size_t)l*H3*Hc, wl + OFF_QKV + (size_t)l*H3*Hc,
            qkv_b + (size_t)l*H3, nullptr, qkv, nullptr, nullptr,
            MROWS, H3, Hc);
        attn_kernel<<<dim3(NHc, Bc), 256, ATTN_SMEM>>>(qkv, wval, cth, ctl);
        hgemm_kernel<2><<<dim3(Hc/128, MB), 256, GEMM_SMEM>>>(
            cth, ctl, wh + OFF_OUT + (size_t)l*Hc*Hc, wl + OFF_OUT + (size_t)l*Hc*Hc,
            out_b + (size_t)l*Hc, x, y, nullptr, nullptr,
            MROWS, Hc, Hc);
        ln_kernel<<<MROWS, 256>>>(y, ln1_s + (size_t)l*Hc, ln1_b + (size_t)l*Hc, x, xh, xl);
        hgemm_kernel<1><<<dim3(FFc/128, MB), 256, GEMM_SMEM>>>(
            xh, xl, wh + OFF_FF1 + (size_t)l*FFc*Hc, wl + OFF_FF1 + (size_t)l*FFc*Hc,
            ff1_b + (size_t)l*FFc, nullptr, nullptr, fh, fl,
            MROWS, FFc, Hc);
        hgemm_kernel<2><<<dim3(Hc/128, MB), 256, GEMM_SMEM>>>(
            fh, fl, wh + OFF_FF2 + (size_t)l*Hc*FFc, wl + OFF_FF2 + (size_t)l*Hc*FFc,
            ff2_b + (size_t)l*Hc, x, y, nullptr, nullptr,
            MROWS, Hc, FFc);
        ln_kernel<<<MROWS, 256>>>(y, ln2_s + (size_t)l*Hc, ln2_b + (size_t)l*Hc, x, xh, xl);
    }
    cls_kernel<<<Bc, 256>>>(x, cls_w, cls_b, out);
}

// round 14
// speedup vs baseline: 1.0750x; 1.0750x over previous
#include <cuda_runtime.h>
#include <cuda_bf16.h>
#include <cstdint>
#include <math.h>

#define Bc    32
#define Sc    512
#define Hc    768
#define Wc    128
#define Gc    4
#define NHc   4
#define HDc   192
#define FFc   2048
#define NLc   2
#define NLABc 6
#define LW    129
#define MROWS (Bc*LW)     /* 4128 */
#define H3    (3*Hc)      /* 2304 */

// weight hi/lo pool offsets (elements)
#define OFF_QKV 0
#define SZ_QKV (NLc*H3*Hc)
#define OFF_OUT (OFF_QKV + SZ_QKV)
#define SZ_OUT (NLc*Hc*Hc)
#define OFF_FF1 (OFF_OUT + SZ_OUT)
#define SZ_FF1 (NLc*FFc*Hc)
#define OFF_FF2 (OFF_FF1 + SZ_FF1)
#define SZ_FF2 (NLc*Hc*FFc)
#define WTOT (OFF_FF2 + SZ_FF2)   /* 11,010,048 */

// ---------------- scratch (device globals; no allocation allowed) ----------
__device__ float g_x  [MROWS*Hc];
__device__ float g_qkv[MROWS*H3];
__device__ float g_y  [MROWS*Hc];
__device__ float g_wvalid[Bc*Wc];
__device__ int   g_mtype;
__device__ int   g_vtype;
__device__ __nv_bfloat16 g_wh[WTOT];
__device__ __nv_bfloat16 g_wl[WTOT];
__device__ __nv_bfloat16 g_xh[MROWS*Hc],  g_xl[MROWS*Hc];
__device__ __nv_bfloat16 g_cth[MROWS*Hc], g_ctl[MROWS*Hc];
__device__ __nv_bfloat16 g_fh[MROWS*FFc], g_fl[MROWS*FFc];

// ---------------- helpers ---------------------------------------------------
__device__ __forceinline__ uint32_t smem_u32(const void* p){
    uint32_t a;
    asm("{ .reg .u64 t; cvta.to.shared.u64 t, %1; cvt.u32.u64 %0, t; }" : "=r"(a) : "l"(p));
    return a;
}
__device__ __forceinline__ void ldsm4(uint32_t* r, uint32_t addr){
    asm volatile("ldmatrix.sync.aligned.m8n8.x4.shared.b16 {%0,%1,%2,%3}, [%4];"
        : "=r"(r[0]), "=r"(r[1]), "=r"(r[2]), "=r"(r[3]) : "r"(addr));
}
__device__ __forceinline__ void mma16816(float* c, const uint32_t* a, uint32_t b0, uint32_t b1){
    asm volatile("mma.sync.aligned.m16n8k16.row.col.f32.bf16.bf16.f32 "
        "{%0,%1,%2,%3}, {%4,%5,%6,%7}, {%8,%9}, {%0,%1,%2,%3};"
        : "+f"(c[0]), "+f"(c[1]), "+f"(c[2]), "+f"(c[3])
        : "r"(a[0]), "r"(a[1]), "r"(a[2]), "r"(a[3]), "r"(b0), "r"(b1));
}
__device__ __forceinline__ void split1(float v, __nv_bfloat16* hp, __nv_bfloat16* lp){
    __nv_bfloat16 h = __float2bfloat16(v);
    *hp = h;
    *lp = __float2bfloat16(v - __bfloat162float(h));
}
__device__ __forceinline__ void split2(float2 v, __nv_bfloat16* hp, __nv_bfloat16* lp){
    __nv_bfloat162 h = __floats2bfloat162_rn(v.x, v.y);
    __nv_bfloat162 l = __floats2bfloat162_rn(v.x - __bfloat162float(h.x),
                                             v.y - __bfloat162float(h.y));
    *(__nv_bfloat162*)hp = h;
    *(__nv_bfloat162*)lp = l;
}

// ---------------- merged weight conversion fp32 -> hi/lo bf16 ---------------
__global__ void wconv_all_kernel(const float* __restrict__ qkv_w,
                                 const float* __restrict__ out_w,
                                 const float* __restrict__ ff1_w,
                                 const float* __restrict__ ff2_w,
                                 __nv_bfloat16* __restrict__ hi,
                                 __nv_bfloat16* __restrict__ lo){
    int i = (blockIdx.x * 256 + threadIdx.x) << 2;
    if (i >= WTOT) return;
    const float* src;
    int off;
    if      (i < OFF_OUT) { src = qkv_w; off = i - OFF_QKV; }
    else if (i < OFF_FF1) { src = out_w; off = i - OFF_OUT; }
    else if (i < OFF_FF2) { src = ff1_w; off = i - OFF_FF1; }
    else                  { src = ff2_w; off = i - OFF_FF2; }
    float4 v = *(const float4*)(src + off);
    __nv_bfloat162 h0 = __floats2bfloat162_rn(v.x, v.y);
    __nv_bfloat162 h1 = __floats2bfloat162_rn(v.z, v.w);
    __nv_bfloat162 l0 = __floats2bfloat162_rn(v.x - __bfloat162float(h0.x),
                                              v.y - __bfloat162float(h0.y));
    __nv_bfloat162 l1 = __floats2bfloat162_rn(v.z - __bfloat162float(h1.x),
                                              v.w - __bfloat162float(h1.y));
    *(uint2*)(hi + i) = make_uint2(*(uint32_t*)&h0, *(uint32_t*)&h1);
    *(uint2*)(lo + i) = make_uint2(*(uint32_t*)&l0, *(uint32_t*)&l1);
}

// ---------------- dtype detection for bool inputs --------------------------
__global__ void detect_kernel(const unsigned int* __restrict__ gm,
                              const unsigned int* __restrict__ wv) {
    __shared__ int fm, bm_, fv, bv;
    int tid = threadIdx.x;
    if (tid == 0) { fm = 0; bm_ = 0; fv = 0; bv = 0; }
    __syncthreads();
    for (int i = tid; i < 4096; i += 256) {
        unsigned v = gm[i];
        if (v == 0x3f800000u) atomicOr(&fm, 1);
        else if (v > 1u)      atomicOr(&bm_, 1);
    }
    for (int i = tid; i < 1024; i += 256) {
        unsigned v = wv[i];
        if (v == 0x3f800000u) atomicOr(&fv, 1);
        else if (v > 1u)      atomicOr(&bv, 1);
    }
    __syncthreads();
    if (tid == 0) {
        g_mtype = fm ? 0 : (bm_ ? 1 : 2);
        g_vtype = fv ? 0 : (bv ? 1 : 2);
    }
}

__device__ __forceinline__ float read_flag(const void* p, int t, int i) {
    if (t == 0) return ((const float*)p)[i];
    if (t == 1) return (float)((const unsigned char*)p)[i];
    return (float)((const int*)p)[i];
}

// ---------------- build x = [cls ; word embeddings] + hi/lo -----------------
__global__ void build_kernel(const float* __restrict__ hidden,
                             const int*   __restrict__ widx,
                             const void*  __restrict__ gmask,
                             const void*  __restrict__ wvin,
                             float* __restrict__ x,
                             __nv_bfloat16* __restrict__ xh,
                             __nv_bfloat16* __restrict__ xl,
                             float* __restrict__ wvalid) {
    int qi  = blockIdx.x;
    int b   = blockIdx.y;
    int tid = threadIdx.x;
    size_t ro = ((size_t)(b*LW) + qi) * Hc;
    float* xr = x + ro;
    if (qi == 0) {
        const float* hr = hidden + (size_t)b * Sc * Hc;
        #pragma unroll
        for (int u = 0; u < 3; u++) {
            float v = hr[tid + 256*u];
            xr[tid + 256*u] = v;
            split1(v, xh + ro + tid + 256*u, xl + ro + tid + 256*u);
        }
        return;
    }
    int w = qi - 1;
    int mt = g_mtype, vt = g_vtype;
    int base = (b*Wc + w) * Gc;
    float mk0 = read_flag(gmask, mt, base+0);
    float mk1 = read_flag(gmask, mt, base+1);
    float mk2 = read_flag(gmask, mt, base+2);
    float mk3 = read_flag(gmask, mt, base+3);
    float cnt = mk0 + mk1 + mk2 + mk3;
    float valid = read_flag(wvin, vt, b*Wc + w);
    if (tid == 0) wvalid[b*Wc + w] = valid;
    float invc = valid / fmaxf(cnt, 1.f);
    const float* hb = hidden + (size_t)b * Sc * Hc;
    const float* r0 = hb + (size_t)widx[base+0] * Hc;
    const float* r1 = hb + (size_t)widx[base+1] * Hc;
    const float* r2 = hb + (size_t)widx[base+2] * Hc;
    const float* r3 = hb + (size_t)widx[base+3] * Hc;
    for (int d = tid; d < Hc; d += 256) {
        float acc = (mk0*r0[d] + mk1*r1[d] + mk2*r2[d] + mk3*r3[d]) * invc;
        xr[d] = acc;
        split1(acc, xh + ro + d, xl + ro + d);
    }
}

// ---------------- split-bf16 mma.sync GEMM (R7 structure: reg prefetch) -----
// C[M,N] = (Ah+Al)[M,K] @ (Bh+Bl)[N,K]^T + bias (+res / relu)
// acc += Ah*Bh + Ah*Bl + Al*Bh. CTA 128x128, BK=32, 8 warps (4m x 2n).
#define ROWB 80
#define MATB (128*ROWB)          /* 10240 B per matrix-half */
#define STAGEB (4*MATB)          /* 40960: Ah,Al,Bh,Bl */
#define GEMM_SMEM (2*STAGEB)     /* 81920 */

template<int EPI>  // 0=bias->f32, 1=bias+relu->hi/lo, 2=bias+res->f32
__global__ __launch_bounds__(256, 1) void hgemm_kernel(
        const __nv_bfloat16* __restrict__ Ah, const __nv_bfloat16* __restrict__ Al,
        const __nv_bfloat16* __restrict__ Bh, const __nv_bfloat16* __restrict__ Bl,
        const float* __restrict__ bias, const float* __restrict__ res,
        float* __restrict__ C,
        __nv_bfloat16* __restrict__ Ch, __nv_bfloat16* __restrict__ Cl,
        int M_, int N_, int K_) {
    extern __shared__ char smc[];
    const uint32_t sb = smem_u32(smc);
    const int tid = threadIdx.x, wid = tid >> 5, lane = tid & 31;
    const int bm = blockIdx.y * 128, bn = blockIdx.x * 128;
    const int wm = (wid & 3) * 32, wn = (wid >> 2) * 64;

    const int r  = tid >> 1;
    const int cb = (tid & 1) << 4;   // 16 bf16 = 32B = 2x uint4
    const bool aok = (bm + r) < M_;
    const __nv_bfloat16* Ahp = Ah + (size_t)(bm + r) * K_ + cb;
    const __nv_bfloat16* Alp = Al + (size_t)(bm + r) * K_ + cb;
    const __nv_bfloat16* Bhp = Bh + (size_t)(bn + r) * K_ + cb;
    const __nv_bfloat16* Blp = Bl + (size_t)(bn + r) * K_ + cb;

    uint4 pa[2], pal[2], pb[2], pbl[2];
    const uint4 z4 = make_uint4(0u,0u,0u,0u);
    const int KT = K_ >> 5;

#define LOADG(kt) do { \
    _Pragma("unroll") \
    for (int u = 0; u < 2; u++) { \
        pa[u]  = aok ? *(const uint4*)(Ahp + (kt)*32 + u*8) : z4; \
        pal[u] = aok ? *(const uint4*)(Alp + (kt)*32 + u*8) : z4; \
        pb[u]  = *(const uint4*)(Bhp + (kt)*32 + u*8); \
        pbl[u] = *(const uint4*)(Blp + (kt)*32 + u*8); \
    } } while(0)

#define STST(st) do { \
    char* _b = smc + (st)*STAGEB; \
    uint32_t _o = (uint32_t)r*ROWB + (uint32_t)cb*2u; \
    _Pragma("unroll") \
    for (int u = 0; u < 2; u++) { \
        *(uint4*)(_b          + _o + u*16u) = pa[u]; \
        *(uint4*)(_b +   MATB + _o + u*16u) = pal[u]; \
        *(uint4*)(_b + 2*MATB + _o + u*16u) = pb[u]; \
        *(uint4*)(_b + 3*MATB + _o + u*16u) = pbl[u]; \
    } } while(0)

    float acc[2][8][4];
    #pragma unroll
    for (int i = 0; i < 2; i++)
        #pragma unroll
        for (int j = 0; j < 8; j++)
            #pragma unroll
            for (int q = 0; q < 4; q++) acc[i][j][q] = 0.f;

    const uint32_t aoff = (uint32_t)(lane & 15) * ROWB + (uint32_t)(lane >> 4) * 16u;

    LOADG(0);
    STST(0);
    if (KT > 1) LOADG(1);
    __syncthreads();

    for (int kt = 0; kt < KT; kt++) {
        const int cur = kt & 1;
        if (kt + 1 < KT) {
            STST(1 - cur);
            if (kt + 2 < KT) LOADG(kt + 2);
        }
        const uint32_t SA = sb + (uint32_t)cur * STAGEB;
        const uint32_t SAh = SA, SAl = SA + MATB, SBh = SA + 2*MATB, SBl = SA + 3*MATB;
        #pragma unroll
        for (int k16 = 0; k16 < 32; k16 += 16) {
            uint32_t ah[2][4], al[2][4];
            ldsm4(ah[0], SAh + (uint32_t)(wm     )*ROWB + aoff + k16*2u);
            ldsm4(ah[1], SAh + (uint32_t)(wm + 16)*ROWB + aoff + k16*2u);
            ldsm4(al[0], SAl + (uint32_t)(wm     )*ROWB + aoff + k16*2u);
            ldsm4(al[1], SAl + (uint32_t)(wm + 16)*ROWB + aoff + k16*2u);
            #pragma unroll
            for (int nf = 0; nf < 4; nf++) {
                uint32_t bh[4], bl[4];
                ldsm4(bh, SBh + (uint32_t)(wn + nf*16)*ROWB + aoff + k16*2u);
                ldsm4(bl, SBl + (uint32_t)(wn + nf*16)*ROWB + aoff + k16*2u);
                #pragma unroll
                for (int mf = 0; mf < 2; mf++) {
                    mma16816(acc[mf][nf*2+0], ah[mf], bh[0], bh[2]);
                    mma16816(acc[mf][nf*2+1], ah[mf], bh[1], bh[3]);
                    mma16816(acc[mf][nf*2+0], ah[mf], bl[0], bl[2]);
                    mma16816(acc[mf][nf*2+1], ah[mf], bl[1], bl[3]);
                    mma16816(acc[mf][nf*2+0], al[mf], bh[0], bh[2]);
                    mma16816(acc[mf][nf*2+1], al[mf], bh[1], bh[3]);
                }
            }
        }
        __syncthreads();
    }

    // epilogue
    #pragma unroll
    for (int mf = 0; mf < 2; mf++) {
        #pragma unroll
        for (int nf = 0; nf < 8; nf++) {
            const int row0 = bm + wm + mf*16 + (lane >> 2);
            const int col  = bn + wn + nf*8 + ((lane & 3) << 1);
            float2 b2 = *(const float2*)(bias + col);
            #pragma unroll
            for (int half = 0; half < 2; half++) {
                const int rw = row0 + half*8;
                if (rw >= M_) continue;
                float2 v = make_float2(acc[mf][nf][half*2+0] + b2.x,
                                       acc[mf][nf][half*2+1] + b2.y);
                const size_t o = (size_t)rw * N_ + col;
                if (EPI == 2) {
                    float2 rr = *(const float2*)(res + o);
                    v.x += rr.x; v.y += rr.y;
                }
                if (EPI == 1) {
                    v.x = fmaxf(v.x, 0.f); v.y = fmaxf(v.y, 0.f);
                    split2(v, Ch + o, Cl + o);
                } else {
                    *(float2*)(C + o) = v;
                }
            }
        }
    }
#undef LOADG
#undef STST
}

// ---------------- attention: one block per (b, h) ---------------------------
#define PADK 196
#define PADL 132
#define ATTN_SMEM ((LW*PADK + HDc*PADL + 8*768 + 132) * 4)

__global__ __launch_bounds__(256, 1) void attn_kernel(
        const float* __restrict__ qkv,
        const float* __restrict__ wvalid,
        __nv_bfloat16* __restrict__ cth,
        __nv_bfloat16* __restrict__ ctl) {
    const int h = blockIdx.x, b = blockIdx.y;
    extern __shared__ float sm[];
    float* Ks   = sm;                    // [LW][196]
    float* Vt   = Ks + LW * PADK;        // [192][132] transposed
    float* sq   = Vt + HDc * PADL;       // 8 warps x 768
    float* madd = sq + 8 * 768;          // 132
    const int tid = threadIdx.x, w = tid >> 5, lane = tid & 31;

    const float* base = qkv + (size_t)(b * LW) * H3 + h * HDc;
    for (int idx = tid; idx < LW * HDc; idx += 256) {
        int rr = idx / HDc, c = idx - rr * HDc;
        Ks[rr * PADK + c] = base[(size_t)rr * H3 + Hc + c];
        Vt[c * PADL + rr] = base[(size_t)rr * H3 + 2*Hc + c];
    }
    if (tid < HDc) {
        Vt[tid * PADL + 129] = 0.f;
        Vt[tid * PADL + 130] = 0.f;
        Vt[tid * PADL + 131] = 0.f;
    }
    for (int kk = tid; kk < LW; kk += 256)
        madd[kk] = (kk == 0 || wvalid[b * Wc + kk - 1] > 0.5f) ? 0.f : -3.0e38f;
    __syncthreads();

    const float scale = 0.07216878364870323f; // 1/sqrt(192)
    float* myq = sq + w * 768;

    for (int q0 = w * 4; q0 < LW; q0 += 32) {
        const int nq = (LW - q0 < 4) ? (LW - q0) : 4;
        #pragma unroll
        for (int t = 0; t < 4; t++) {
            if (t < nq) {
                const float* qr = qkv + (size_t)(b * LW + q0 + t) * H3 + h * HDc;
                for (int j = lane; j < 48; j += 32)
                    *(float4*)&myq[t*192 + j*4] = *(const float4*)&qr[j*4];
            } else {
                for (int j = lane; j < 48; j += 32)
                    *(float4*)&myq[t*192 + j*4] = make_float4(0.f,0.f,0.f,0.f);
            }
        }
        __syncwarp();

        float s[4][4];
        #pragma unroll
        for (int t = 0; t < 4; t++)
            #pragma unroll
            for (int i = 0; i < 4; i++) s[t][i] = 0.f;

        #pragma unroll 4
        for (int d4 = 0; d4 < HDc; d4 += 4) {
            float4 qv[4];
            qv[0] = *(const float4*)&myq[0*192 + d4];
            qv[1] = *(const float4*)&myq[1*192 + d4];
            qv[2] = *(const float4*)&myq[2*192 + d4];
            qv[3] = *(const float4*)&myq[3*192 + d4];
            float4 kv[4];
            kv[0] = *(const float4*)&Ks[(lane      ) * PADK + d4];
            kv[1] = *(const float4*)&Ks[(lane + 32 ) * PADK + d4];
            kv[2] = *(const float4*)&Ks[(lane + 64 ) * PADK + d4];
            kv[3] = *(const float4*)&Ks[(lane + 96 ) * PADK + d4];
            #pragma unroll
            for (int t = 0; t < 4; t++)
                #pragma unroll
                for (int i = 0; i < 4; i++)
                    s[t][i] += qv[t].x*kv[i].x + qv[t].y*kv[i].y
                             + qv[t].z*kv[i].z + qv[t].w*kv[i].w;
        }

        float s128[4];
        #pragma unroll
        for (int t = 0; t < 4; t++) {
            float p = 0.f;
            #pragma unroll
            for (int j = 0; j < 6; j++)
                p += myq[t*192 + lane + 32*j] * Ks[128 * PADK + lane + 32*j];
            #pragma unroll
            for (int o = 16; o > 0; o >>= 1) p += __shfl_xor_sync(0xffffffffu, p, o);
            s128[t] = p;
        }

        const float m0 = madd[lane], m1 = madd[lane+32], m2 = madd[lane+64], m3 = madd[lane+96];
        const float m128 = madd[128];
        float e[4][4], e128[4], inv[4];
        #pragma unroll
        for (int t = 0; t < 4; t++) {
            s[t][0] = s[t][0]*scale + m0;
            s[t][1] = s[t][1]*scale + m1;
            s[t][2] = s[t][2]*scale + m2;
            s[t][3] = s[t][3]*scale + m3;
            s128[t] = s128[t]*scale + m128;
            float mm = fmaxf(fmaxf(s[t][0], s[t][1]), fmaxf(s[t][2], s[t][3]));
            #pragma unroll
            for (int o = 16; o > 0; o >>= 1) mm = fmaxf(mm, __shfl_xor_sync(0xffffffffu, mm, o));
            mm = fmaxf(mm, s128[t]);
            e[t][0] = expf(s[t][0] - mm); e[t][1] = expf(s[t][1] - mm);
            e[t][2] = expf(s[t][2] - mm); e[t][3] = expf(s[t][3] - mm);
            float ss = e[t][0] + e[t][1] + e[t][2] + e[t][3];
            #pragma unroll
            for (int o = 16; o > 0; o >>= 1) ss += __shfl_xor_sync(0xffffffffu, ss, o);
            e128[t] = expf(s128[t] - mm);
            ss += e128[t];
            inv[t] = 1.f / ss;
        }
        __syncwarp();
        #pragma unroll
        for (int t = 0; t < 4; t++) {
            myq[t*192 + lane     ] = e[t][0];
            myq[t*192 + lane + 32] = e[t][1];
            myq[t*192 + lane + 64] = e[t][2];
            myq[t*192 + lane + 96] = e[t][3];
            if (lane == 0) myq[t*192 + 128] = e128[t];
            if (lane >= 1 && lane <= 3) myq[t*192 + 128 + lane] = 0.f;
        }
        __syncwarp();

        // AV: acc[t][j] over d = lane+32j, float4 across keys
        float acc[4][6];
        #pragma unroll
        for (int t = 0; t < 4; t++)
            #pragma unroll
            for (int j = 0; j < 6; j++) acc[t][j] = 0.f;
        #pragma unroll 4
        for (int kk4 = 0; kk4 < 132; kk4 += 4) {
            float4 p0 = *(const float4*)&myq[0*192 + kk4];
            float4 p1 = *(const float4*)&myq[1*192 + kk4];
            float4 p2 = *(const float4*)&myq[2*192 + kk4];
            float4 p3 = *(const float4*)&myq[3*192 + kk4];
            #pragma unroll
            for (int j = 0; j < 6; j++) {
                float4 v = *(const float4*)&Vt[(lane + 32*j) * PADL + kk4];
                acc[0][j] += p0.x*v.x + p0.y*v.y + p0.z*v.z + p0.w*v.w;
                acc[1][j] += p1.x*v.x + p1.y*v.y + p1.z*v.z + p1.w*v.w;
                acc[2][j] += p2.x*v.x + p2.y*v.y + p2.z*v.z + p2.w*v.w;
                acc[3][j] += p3.x*v.x + p3.y*v.y + p3.z*v.z + p3.w*v.w;
            }
        }
        for (int t = 0; t < nq; t++) {
            size_t ro = (size_t)(b * LW + q0 + t) * Hc + h * HDc;
            #pragma unroll
            for (int j = 0; j < 6; j++) {
                float val = acc[t][j] * inv[t];
                split1(val, cth + ro + lane + 32*j, ctl + ro + lane + 32*j);
            }
        }
        __syncwarp();
    }
}

// ---------------- layernorm over H=768 per row + hi/lo ----------------------
__global__ void ln_kernel(const float* __restrict__ y,
                          const float* __restrict__ s,
                          const float* __restrict__ bi,
                          float* __restrict__ x,
                          __nv_bfloat16* __restrict__ xh,
                          __nv_bfloat16* __restrict__ xl) {
    int row = blockIdx.x;
    int tid = threadIdx.x;
    __shared__ float red[256];
    const float* yr = y + (size_t)row * Hc;
    float v0 = yr[tid], v1 = yr[tid+256], v2 = yr[tid+512];
    red[tid] = v0 + v1 + v2; __syncthreads();
    for (int o = 128; o > 0; o >>= 1) { if (tid < o) red[tid] += red[tid+o]; __syncthreads(); }
    float mean = red[0] * (1.f/768.f);
    __syncthreads();
    float d0 = v0-mean, d1 = v1-mean, d2 = v2-mean;
    red[tid] = d0*d0 + d1*d1 + d2*d2; __syncthreads();
    for (int o = 128; o > 0; o >>= 1) { if (tid < o) red[tid] += red[tid+o]; __syncthreads(); }
    float inv = rsqrtf(red[0] * (1.f/768.f) + 1e-5f);
    size_t ro = (size_t)row * Hc;
    float o0 = d0*inv*s[tid]     + bi[tid];
    float o1 = d1*inv*s[tid+256] + bi[tid+256];
    float o2 = d2*inv*s[tid+512] + bi[tid+512];
    x[ro+tid] = o0; x[ro+tid+256] = o1; x[ro+tid+512] = o2;
    split1(o0, xh + ro + tid,     xl + ro + tid);
    split1(o1, xh + ro + tid+256, xl + ro + tid+256);
    split1(o2, xh + ro + tid+512, xl + ro + tid+512);
}

// ---------------- classifier + pooled copy ----------------------------------
__global__ void cls_kernel(const float* __restrict__ x,
                           const float* __restrict__ cw,
                           const float* __restrict__ cb,
                           float* __restrict__ out) {
    int b = blockIdx.x;
    int tid = threadIdx.x;
    __shared__ float red[256];
    const float* row = x + (size_t)(b*LW) * Hc;
    out[Bc*NLABc + b*Hc + tid]     = row[tid];
    out[Bc*NLABc + b*Hc + tid+256] = row[tid+256];
    out[Bc*NLABc + b*Hc + tid+512] = row[tid+512];
    for (int lab = 0; lab < NLABc; lab++) {
        const float* wr = cw + lab*Hc;
        float s = row[tid]*wr[tid] + row[tid+256]*wr[tid+256] + row[tid+512]*wr[tid+512];
        red[tid] = s; __syncthreads();
        for (int o = 128; o > 0; o >>= 1) { if (tid < o) red[tid] += red[tid+o]; __syncthreads(); }
        if (tid == 0) out[b*NLABc + lab] = red[0] + cb[lab];
        __syncthreads();
    }
}

// ---------------- launch -----------------------------------------------------
extern "C" void kernel_launch(void* const* d_in, const int* in_sizes, int n_in,
                              void* d_out, int out_size) {
    (void)in_sizes; (void)n_in; (void)out_size;
    const float* hidden = (const float*)d_in[0];
    const int*   widx   = (const int*)  d_in[1];
    const void*  gmask  = d_in[2];
    const void*  wvin   = d_in[3];
    const float* qkv_w  = (const float*)d_in[4];
    const float* qkv_b  = (const float*)d_in[5];
    const float* out_w  = (const float*)d_in[6];
    const float* out_b  = (const float*)d_in[7];
    const float* ff1_w  = (const float*)d_in[8];
    const float* ff1_b  = (const float*)d_in[9];
    const float* ff2_w  = (const float*)d_in[10];
    const float* ff2_b  = (const float*)d_in[11];
    const float* ln1_s  = (const float*)d_in[12];
    const float* ln1_b  = (const float*)d_in[13];
    const float* ln2_s  = (const float*)d_in[14];
    const float* ln2_b  = (const float*)d_in[15];
    const float* cls_w  = (const float*)d_in[16];
    const float* cls_b  = (const float*)d_in[17];
    float* out = (float*)d_out;

    float *x, *qkv, *y, *wval;
    __nv_bfloat16 *wh, *wl, *xh, *xl, *cth, *ctl, *fh, *fl;
    cudaGetSymbolAddress((void**)&x,    g_x);
    cudaGetSymbolAddress((void**)&qkv,  g_qkv);
    cudaGetSymbolAddress((void**)&y,    g_y);
    cudaGetSymbolAddress((void**)&wval, g_wvalid);
    cudaGetSymbolAddress((void**)&wh,   g_wh);
    cudaGetSymbolAddress((void**)&wl,   g_wl);
    cudaGetSymbolAddress((void**)&xh,   g_xh);
    cudaGetSymbolAddress((void**)&xl,   g_xl);
    cudaGetSymbolAddress((void**)&cth,  g_cth);
    cudaGetSymbolAddress((void**)&ctl,  g_ctl);
    cudaGetSymbolAddress((void**)&fh,   g_fh);
    cudaGetSymbolAddress((void**)&fl,   g_fl);

    cudaFuncSetAttribute(hgemm_kernel<0>, cudaFuncAttributeMaxDynamicSharedMemorySize, (int)GEMM_SMEM);
    cudaFuncSetAttribute(hgemm_kernel<1>, cudaFuncAttributeMaxDynamicSharedMemorySize, (int)GEMM_SMEM);
    cudaFuncSetAttribute(hgemm_kernel<2>, cudaFuncAttributeMaxDynamicSharedMemorySize, (int)GEMM_SMEM);
    cudaFuncSetAttribute(attn_kernel,     cudaFuncAttributeMaxDynamicSharedMemorySize, (int)ATTN_SMEM);

    // weight conversion (once per launch, single merged launch)
    wconv_all_kernel<<<(WTOT/4 + 255)/256, 256>>>(qkv_w, out_w, ff1_w, ff2_w, wh, wl);

    detect_kernel<<<1, 256>>>((const unsigned int*)gmask, (const unsigned int*)wvin);
    build_kernel<<<dim3(LW, Bc), 256>>>(hidden, widx, gmask, wvin, x, xh, xl, wval);

    const int MB = (MROWS + 127) / 128;  // 33
    for (int l = 0; l < NLc; l++) {
        hgemm_kernel<0><<<dim3(H3/128, MB), 256, GEMM_SMEM>>>(
            xh, xl, wh + OFF_QKV + (size_t)l*H3*Hc, wl + OFF_QKV + (size_t)l*H3*Hc,
            qkv_b + (size_t)l*H3, nullptr, qkv, nullptr, nullptr,
            MROWS, H3, Hc);
        attn_kernel<<<dim3(NHc, Bc), 256, ATTN_SMEM>>>(qkv, wval, cth, ctl);
        hgemm_kernel<2><<<dim3(Hc/128, MB), 256, GEMM_SMEM>>>(
            cth, ctl, wh + OFF_OUT + (size_t)l*Hc*Hc, wl + OFF_OUT + (size_t)l*Hc*Hc,
            out_b + (size_t)l*Hc, x, y, nullptr, nullptr,
            MROWS, Hc, Hc);
        ln_kernel<<<MROWS, 256>>>(y, ln1_s + (size_t)l*Hc, ln1_b + (size_t)l*Hc, x, xh, xl);
        hgemm_kernel<1><<<dim3(FFc/128, MB), 256, GEMM_SMEM>>>(
            xh, xl, wh + OFF_FF1 + (size_t)l*FFc*Hc, wl + OFF_FF1 + (size_t)l*FFc*Hc,
            ff1_b + (size_t)l*FFc, nullptr, nullptr, fh, fl,
            MROWS, FFc, Hc);
        hgemm_kernel<2><<<dim3(Hc/128, MB), 256, GEMM_SMEM>>>(
            fh, fl, wh + OFF_FF2 + (size_t)l*Hc*FFc, wl + OFF_FF2 + (size_t)l*Hc*FFc,
            ff2_b + (size_t)l*Hc, x, y, nullptr, nullptr,
            MROWS, Hc, FFc);
        ln_kernel<<<MROWS, 256>>>(y, ln2_s + (size_t)l*Hc, ln2_b + (size_t)l*Hc, x, xh, xl);
    }
    cls_kernel<<<Bc, 256>>>(x, cls_w, cls_b, out);
}

// round 16
// speedup vs baseline: 1.0867x; 1.0109x over previous
#include <cuda_runtime.h>
#include <cuda_bf16.h>
#include <cstdint>
#include <math.h>

#define Bc    32
#define Sc    512
#define Hc    768
#define Wc    128
#define Gc    4
#define NHc   4
#define HDc   192
#define FFc   2048
#define NLc   2
#define NLABc 6
#define LW    129
#define MROWS (Bc*LW)     /* 4128 */
#define H3    (3*Hc)      /* 2304 */

// weight hi/lo pool offsets (elements)
#define OFF_QKV 0
#define SZ_QKV (NLc*H3*Hc)
#define OFF_OUT (OFF_QKV + SZ_QKV)
#define SZ_OUT (NLc*Hc*Hc)
#define OFF_FF1 (OFF_OUT + SZ_OUT)
#define SZ_FF1 (NLc*FFc*Hc)
#define OFF_FF2 (OFF_FF1 + SZ_FF1)
#define SZ_FF2 (NLc*Hc*FFc)
#define WTOT (OFF_FF2 + SZ_FF2)   /* 11,010,048 */

// ---------------- scratch (device globals; no allocation allowed) ----------
__device__ float g_x  [MROWS*Hc];
__device__ float g_qkv[MROWS*H3];
__device__ float g_y  [MROWS*Hc];
__device__ float g_wvalid[Bc*Wc];
__device__ int   g_mtype;
__device__ int   g_vtype;
__device__ __nv_bfloat16 g_wh[WTOT];
__device__ __nv_bfloat16 g_wl[WTOT];
__device__ __nv_bfloat16 g_xh[MROWS*Hc],  g_xl[MROWS*Hc];
__device__ __nv_bfloat16 g_cth[MROWS*Hc], g_ctl[MROWS*Hc];
__device__ __nv_bfloat16 g_fh[MROWS*FFc], g_fl[MROWS*FFc];

// ---------------- helpers ---------------------------------------------------
__device__ __forceinline__ uint32_t smem_u32(const void* p){
    uint32_t a;
    asm("{ .reg .u64 t; cvta.to.shared.u64 t, %1; cvt.u32.u64 %0, t; }" : "=r"(a) : "l"(p));
    return a;
}
__device__ __forceinline__ void ldsm4(uint32_t* r, uint32_t addr){
    asm volatile("ldmatrix.sync.aligned.m8n8.x4.shared.b16 {%0,%1,%2,%3}, [%4];"
        : "=r"(r[0]), "=r"(r[1]), "=r"(r[2]), "=r"(r[3]) : "r"(addr));
}
__device__ __forceinline__ void mma16816(float* c, const uint32_t* a, uint32_t b0, uint32_t b1){
    asm volatile("mma.sync.aligned.m16n8k16.row.col.f32.bf16.bf16.f32 "
        "{%0,%1,%2,%3}, {%4,%5,%6,%7}, {%8,%9}, {%0,%1,%2,%3};"
        : "+f"(c[0]), "+f"(c[1]), "+f"(c[2]), "+f"(c[3])
        : "r"(a[0]), "r"(a[1]), "r"(a[2]), "r"(a[3]), "r"(b0), "r"(b1));
}
__device__ __forceinline__ void split1(float v, __nv_bfloat16* hp, __nv_bfloat16* lp){
    __nv_bfloat16 h = __float2bfloat16(v);
    *hp = h;
    *lp = __float2bfloat16(v - __bfloat162float(h));
}
__device__ __forceinline__ void split2(float2 v, __nv_bfloat16* hp, __nv_bfloat16* lp){
    __nv_bfloat162 h = __floats2bfloat162_rn(v.x, v.y);
    __nv_bfloat162 l = __floats2bfloat162_rn(v.x - __bfloat162float(h.x),
                                             v.y - __bfloat162float(h.y));
    *(__nv_bfloat162*)hp = h;
    *(__nv_bfloat162*)lp = l;
}

// ---------------- merged weight conversion fp32 -> hi/lo bf16 ---------------
__global__ void wconv_all_kernel(const float* __restrict__ qkv_w,
                                 const float* __restrict__ out_w,
                                 const float* __restrict__ ff1_w,
                                 const float* __restrict__ ff2_w,
                                 __nv_bfloat16* __restrict__ hi,
                                 __nv_bfloat16* __restrict__ lo){
    int i = (blockIdx.x * 256 + threadIdx.x) << 2;
    if (i >= WTOT) return;
    const float* src;
    int off;
    if      (i < OFF_OUT) { src = qkv_w; off = i - OFF_QKV; }
    else if (i < OFF_FF1) { src = out_w; off = i - OFF_OUT; }
    else if (i < OFF_FF2) { src = ff1_w; off = i - OFF_FF1; }
    else                  { src = ff2_w; off = i - OFF_FF2; }
    float4 v = *(const float4*)(src + off);
    __nv_bfloat162 h0 = __floats2bfloat162_rn(v.x, v.y);
    __nv_bfloat162 h1 = __floats2bfloat162_rn(v.z, v.w);
    __nv_bfloat162 l0 = __floats2bfloat162_rn(v.x - __bfloat162float(h0.x),
                                              v.y - __bfloat162float(h0.y));
    __nv_bfloat162 l1 = __floats2bfloat162_rn(v.z - __bfloat162float(h1.x),
                                              v.w - __bfloat162float(h1.y));
    *(uint2*)(hi + i) = make_uint2(*(uint32_t*)&h0, *(uint32_t*)&h1);
    *(uint2*)(lo + i) = make_uint2(*(uint32_t*)&l0, *(uint32_t*)&l1);
}

// ---------------- dtype detection for bool inputs --------------------------
__global__ void detect_kernel(const unsigned int* __restrict__ gm,
                              const unsigned int* __restrict__ wv) {
    __shared__ int fm, bm_, fv, bv;
    int tid = threadIdx.x;
    if (tid == 0) { fm = 0; bm_ = 0; fv = 0; bv = 0; }
    __syncthreads();
    for (int i = tid; i < 4096; i += 256) {
        unsigned v = gm[i];
        if (v == 0x3f800000u) atomicOr(&fm, 1);
        else if (v > 1u)      atomicOr(&bm_, 1);
    }
    for (int i = tid; i < 1024; i += 256) {
        unsigned v = wv[i];
        if (v == 0x3f800000u) atomicOr(&fv, 1);
        else if (v > 1u)      atomicOr(&bv, 1);
    }
    __syncthreads();
    if (tid == 0) {
        g_mtype = fm ? 0 : (bm_ ? 1 : 2);
        g_vtype = fv ? 0 : (bv ? 1 : 2);
    }
}

__device__ __forceinline__ float read_flag(const void* p, int t, int i) {
    if (t == 0) return ((const float*)p)[i];
    if (t == 1) return (float)((const unsigned char*)p)[i];
    return (float)((const int*)p)[i];
}

// ---------------- build x = [cls ; word embeddings] + hi/lo -----------------
__global__ void build_kernel(const float* __restrict__ hidden,
                             const int*   __restrict__ widx,
                             const void*  __restrict__ gmask,
                             const void*  __restrict__ wvin,
                             float* __restrict__ x,
                             __nv_bfloat16* __restrict__ xh,
                             __nv_bfloat16* __restrict__ xl,
                             float* __restrict__ wvalid) {
    int qi  = blockIdx.x;
    int b   = blockIdx.y;
    int tid = threadIdx.x;
    size_t ro = ((size_t)(b*LW) + qi) * Hc;
    float* xr = x + ro;
    if (qi == 0) {
        const float* hr = hidden + (size_t)b * Sc * Hc;
        #pragma unroll
        for (int u = 0; u < 3; u++) {
            float v = hr[tid + 256*u];
            xr[tid + 256*u] = v;
            split1(v, xh + ro + tid + 256*u, xl + ro + tid + 256*u);
        }
        return;
    }
    int w = qi - 1;
    int mt = g_mtype, vt = g_vtype;
    int base = (b*Wc + w) * Gc;
    float mk0 = read_flag(gmask, mt, base+0);
    float mk1 = read_flag(gmask, mt, base+1);
    float mk2 = read_flag(gmask, mt, base+2);
    float mk3 = read_flag(gmask, mt, base+3);
    float cnt = mk0 + mk1 + mk2 + mk3;
    float valid = read_flag(wvin, vt, b*Wc + w);
    if (tid == 0) wvalid[b*Wc + w] = valid;
    float invc = valid / fmaxf(cnt, 1.f);
    const float* hb = hidden + (size_t)b * Sc * Hc;
    const float* r0 = hb + (size_t)widx[base+0] * Hc;
    const float* r1 = hb + (size_t)widx[base+1] * Hc;
    const float* r2 = hb + (size_t)widx[base+2] * Hc;
    const float* r3 = hb + (size_t)widx[base+3] * Hc;
    for (int d = tid; d < Hc; d += 256) {
        float acc = (mk0*r0[d] + mk1*r1[d] + mk2*r2[d] + mk3*r3[d]) * invc;
        xr[d] = acc;
        split1(acc, xh + ro + d, xl + ro + d);
    }
}

// ---------------- split-bf16 mma.sync GEMM (R14 structure: reg prefetch) ----
// C[M,N] = (Ah+Al)[M,K] @ (Bh+Bl)[N,K]^T + bias (+res / relu)
// acc += Ah*Bh + Ah*Bl + Al*Bh. CTA 128x128, BK=32, 8 warps (4m x 2n).
#define ROWB 80
#define MATB (128*ROWB)          /* 10240 B per matrix-half */
#define STAGEB (4*MATB)          /* 40960: Ah,Al,Bh,Bl */
#define GEMM_SMEM (2*STAGEB)     /* 81920 */

template<int EPI>  // 0=bias->f32, 1=bias+relu->hi/lo, 2=bias+res->f32
__global__ __launch_bounds__(256, 1) void hgemm_kernel(
        const __nv_bfloat16* __restrict__ Ah, const __nv_bfloat16* __restrict__ Al,
        const __nv_bfloat16* __restrict__ Bh, const __nv_bfloat16* __restrict__ Bl,
        const float* __restrict__ bias, const float* __restrict__ res,
        float* __restrict__ C,
        __nv_bfloat16* __restrict__ Ch, __nv_bfloat16* __restrict__ Cl,
        int M_, int N_, int K_) {
    extern __shared__ char smc[];
    const uint32_t sb = smem_u32(smc);
    const int tid = threadIdx.x, wid = tid >> 5, lane = tid & 31;
    const int bm = blockIdx.y * 128, bn = blockIdx.x * 128;
    const int wm = (wid & 3) * 32, wn = (wid >> 2) * 64;

    const int r  = tid >> 1;
    const int cb = (tid & 1) << 4;   // 16 bf16 = 32B = 2x uint4
    const bool aok = (bm + r) < M_;
    const __nv_bfloat16* Ahp = Ah + (size_t)(bm + r) * K_ + cb;
    const __nv_bfloat16* Alp = Al + (size_t)(bm + r) * K_ + cb;
    const __nv_bfloat16* Bhp = Bh + (size_t)(bn + r) * K_ + cb;
    const __nv_bfloat16* Blp = Bl + (size_t)(bn + r) * K_ + cb;

    uint4 pa[2], pal[2], pb[2], pbl[2];
    const uint4 z4 = make_uint4(0u,0u,0u,0u);
    const int KT = K_ >> 5;

#define LOADG(kt) do { \
    _Pragma("unroll") \
    for (int u = 0; u < 2; u++) { \
        pa[u]  = aok ? *(const uint4*)(Ahp + (kt)*32 + u*8) : z4; \
        pal[u] = aok ? *(const uint4*)(Alp + (kt)*32 + u*8) : z4; \
        pb[u]  = *(const uint4*)(Bhp + (kt)*32 + u*8); \
        pbl[u] = *(const uint4*)(Blp + (kt)*32 + u*8); \
    } } while(0)

#define STST(st) do { \
    char* _b = smc + (st)*STAGEB; \
    uint32_t _o = (uint32_t)r*ROWB + (uint32_t)cb*2u; \
    _Pragma("unroll") \
    for (int u = 0; u < 2; u++) { \
        *(uint4*)(_b          + _o + u*16u) = pa[u]; \
        *(uint4*)(_b +   MATB + _o + u*16u) = pal[u]; \
        *(uint4*)(_b + 2*MATB + _o + u*16u) = pb[u]; \
        *(uint4*)(_b + 3*MATB + _o + u*16u) = pbl[u]; \
    } } while(0)

    float acc[2][8][4];
    #pragma unroll
    for (int i = 0; i < 2; i++)
        #pragma unroll
        for (int j = 0; j < 8; j++)
            #pragma unroll
            for (int q = 0; q < 4; q++) acc[i][j][q] = 0.f;

    const uint32_t aoff = (uint32_t)(lane & 15) * ROWB + (uint32_t)(lane >> 4) * 16u;

    LOADG(0);
    STST(0);
    if (KT > 1) LOADG(1);
    __syncthreads();

    for (int kt = 0; kt < KT; kt++) {
        const int cur = kt & 1;
        if (kt + 1 < KT) {
            STST(1 - cur);
            if (kt + 2 < KT) LOADG(kt + 2);
        }
        const uint32_t SA = sb + (uint32_t)cur * STAGEB;
        const uint32_t SAh = SA, SAl = SA + MATB, SBh = SA + 2*MATB, SBl = SA + 3*MATB;
        #pragma unroll
        for (int k16 = 0; k16 < 32; k16 += 16) {
            uint32_t ah[2][4], al[2][4];
            ldsm4(ah[0], SAh + (uint32_t)(wm     )*ROWB + aoff + k16*2u);
            ldsm4(ah[1], SAh + (uint32_t)(wm + 16)*ROWB + aoff + k16*2u);
            ldsm4(al[0], SAl + (uint32_t)(wm     )*ROWB + aoff + k16*2u);
            ldsm4(al[1], SAl + (uint32_t)(wm + 16)*ROWB + aoff + k16*2u);
            #pragma unroll
            for (int nf = 0; nf < 4; nf++) {
                uint32_t bh[4], bl[4];
                ldsm4(bh, SBh + (uint32_t)(wn + nf*16)*ROWB + aoff + k16*2u);
                ldsm4(bl, SBl + (uint32_t)(wn + nf*16)*ROWB + aoff + k16*2u);
                #pragma unroll
                for (int mf = 0; mf < 2; mf++) {
                    mma16816(acc[mf][nf*2+0], ah[mf], bh[0], bh[2]);
                    mma16816(acc[mf][nf*2+1], ah[mf], bh[1], bh[3]);
                    mma16816(acc[mf][nf*2+0], ah[mf], bl[0], bl[2]);
                    mma16816(acc[mf][nf*2+1], ah[mf], bl[1], bl[3]);
                    mma16816(acc[mf][nf*2+0], al[mf], bh[0], bh[2]);
                    mma16816(acc[mf][nf*2+1], al[mf], bh[1], bh[3]);
                }
            }
        }
        __syncthreads();
    }

    // epilogue
    #pragma unroll
    for (int mf = 0; mf < 2; mf++) {
        #pragma unroll
        for (int nf = 0; nf < 8; nf++) {
            const int row0 = bm + wm + mf*16 + (lane >> 2);
            const int col  = bn + wn + nf*8 + ((lane & 3) << 1);
            float2 b2 = *(const float2*)(bias + col);
            #pragma unroll
            for (int half = 0; half < 2; half++) {
                const int rw = row0 + half*8;
                if (rw >= M_) continue;
                float2 v = make_float2(acc[mf][nf][half*2+0] + b2.x,
                                       acc[mf][nf][half*2+1] + b2.y);
                const size_t o = (size_t)rw * N_ + col;
                if (EPI == 2) {
                    float2 rr = *(const float2*)(res + o);
                    v.x += rr.x; v.y += rr.y;
                }
                if (EPI == 1) {
                    v.x = fmaxf(v.x, 0.f); v.y = fmaxf(v.y, 0.f);
                    split2(v, Ch + o, Cl + o);
                } else {
                    *(float2*)(C + o) = v;
                }
            }
        }
    }
#undef LOADG
#undef STST
}

// ---------------- attention: one block per (b, h), 384 threads --------------
// Ks [129][196] f32, Vt [192][132] f32 (transposed), prb 12 warps x 4q x 132,
// q read directly from global (L2) in QK loop. 3 warps/SMSP for latency hiding.
#define PADK 196
#define PADL 132
#define ATW  12
#define ATTN_SMEM ((LW*PADK + HDc*PADL + ATW*4*PADL + PADL) * 4)

__global__ __launch_bounds__(384, 1) void attn_kernel(
        const float* __restrict__ qkv,
        const float* __restrict__ wvalid,
        __nv_bfloat16* __restrict__ cth,
        __nv_bfloat16* __restrict__ ctl) {
    const int h = blockIdx.x, b = blockIdx.y;
    extern __shared__ float sm[];
    float* Ks   = sm;                     // [129][196]
    float* Vt   = Ks + LW * PADK;         // [192][132]
    float* prb  = Vt + HDc * PADL;        // [12][4][132]
    float* madd = prb + ATW * 4 * PADL;   // [132]
    const int tid = threadIdx.x, w = tid >> 5, lane = tid & 31;

    const float* base = qkv + (size_t)(b * LW) * H3 + h * HDc;
    for (int idx = tid; idx < LW * HDc; idx += 384) {
        int rr = idx / HDc, c = idx - rr * HDc;
        Ks[rr * PADK + c] = base[(size_t)rr * H3 + Hc + c];
        Vt[c * PADL + rr] = base[(size_t)rr * H3 + 2*Hc + c];
    }
    if (tid < HDc) {
        Vt[tid * PADL + 129] = 0.f;
        Vt[tid * PADL + 130] = 0.f;
        Vt[tid * PADL + 131] = 0.f;
    }
    for (int kk = tid; kk < LW; kk += 384)
        madd[kk] = (kk == 0 || wvalid[b * Wc + kk - 1] > 0.5f) ? 0.f : -3.0e38f;
    __syncthreads();

    const float scale = 0.07216878364870323f; // 1/sqrt(192)
    float* prw = prb + w * 4 * PADL;

    for (int q0 = w * 4; q0 < LW; q0 += 48) {
        const int nq = (LW - q0 < 4) ? (LW - q0) : 4;
        // q row pointers (clamped for t >= nq; values unused)
        const float* qp[4];
        #pragma unroll
        for (int t = 0; t < 4; t++) {
            int qi = q0 + ((t < nq) ? t : 0);
            qp[t] = qkv + (size_t)(b * LW + qi) * H3 + h * HDc;
        }

        float s[4][4];
        #pragma unroll
        for (int t = 0; t < 4; t++)
            #pragma unroll
            for (int i = 0; i < 4; i++) s[t][i] = 0.f;

        #pragma unroll 4
        for (int d4 = 0; d4 < HDc; d4 += 4) {
            float4 qv[4];
            qv[0] = *(const float4*)(qp[0] + d4);
            qv[1] = *(const float4*)(qp[1] + d4);
            qv[2] = *(const float4*)(qp[2] + d4);
            qv[3] = *(const float4*)(qp[3] + d4);
            float4 kv[4];
            kv[0] = *(const float4*)&Ks[(lane      ) * PADK + d4];
            kv[1] = *(const float4*)&Ks[(lane + 32 ) * PADK + d4];
            kv[2] = *(const float4*)&Ks[(lane + 64 ) * PADK + d4];
            kv[3] = *(const float4*)&Ks[(lane + 96 ) * PADK + d4];
            #pragma unroll
            for (int t = 0; t < 4; t++)
                #pragma unroll
                for (int i = 0; i < 4; i++)
                    s[t][i] += qv[t].x*kv[i].x + qv[t].y*kv[i].y
                             + qv[t].z*kv[i].z + qv[t].w*kv[i].w;
        }

        float s128[4];
        #pragma unroll
        for (int t = 0; t < 4; t++) {
            float p = 0.f;
            #pragma unroll
            for (int j = 0; j < 6; j++)
                p += qp[t][lane + 32*j] * Ks[128 * PADK + lane + 32*j];
            #pragma unroll
            for (int o = 16; o > 0; o >>= 1) p += __shfl_xor_sync(0xffffffffu, p, o);
            s128[t] = p;
        }

        const float m0 = madd[lane], m1 = madd[lane+32], m2 = madd[lane+64], m3 = madd[lane+96];
        const float m128 = madd[128];
        float e[4][4], e128[4], inv[4];
        #pragma unroll
        for (int t = 0; t < 4; t++) {
            s[t][0] = s[t][0]*scale + m0;
            s[t][1] = s[t][1]*scale + m1;
            s[t][2] = s[t][2]*scale + m2;
            s[t][3] = s[t][3]*scale + m3;
            s128[t] = s128[t]*scale + m128;
            float mm = fmaxf(fmaxf(s[t][0], s[t][1]), fmaxf(s[t][2], s[t][3]));
            #pragma unroll
            for (int o = 16; o > 0; o >>= 1) mm = fmaxf(mm, __shfl_xor_sync(0xffffffffu, mm, o));
            mm = fmaxf(mm, s128[t]);
            e[t][0] = __expf(s[t][0] - mm); e[t][1] = __expf(s[t][1] - mm);
            e[t][2] = __expf(s[t][2] - mm); e[t][3] = __expf(s[t][3] - mm);
            float ss = e[t][0] + e[t][1] + e[t][2] + e[t][3];
            #pragma unroll
            for (int o = 16; o > 0; o >>= 1) ss += __shfl_xor_sync(0xffffffffu, ss, o);
            e128[t] = __expf(s128[t] - mm);
            ss += e128[t];
            inv[t] = 1.f / ss;
        }
        __syncwarp();
        #pragma unroll
        for (int t = 0; t < 4; t++) {
            prw[t*PADL + lane     ] = e[t][0];
            prw[t*PADL + lane + 32] = e[t][1];
            prw[t*PADL + lane + 64] = e[t][2];
            prw[t*PADL + lane + 96] = e[t][3];
            if (lane == 0) prw[t*PADL + 128] = e128[t];
            if (lane >= 1 && lane <= 3) prw[t*PADL + 128 + lane] = 0.f;
        }
        __syncwarp();

        // AV: acc[t][j] over d = lane+32j, float4 across keys
        float acc[4][6];
        #pragma unroll
        for (int t = 0; t < 4; t++)
            #pragma unroll
            for (int j = 0; j < 6; j++) acc[t][j] = 0.f;
        #pragma unroll 4
        for (int kk4 = 0; kk4 < PADL; kk4 += 4) {
            float4 p0 = *(const float4*)&prw[0*PADL + kk4];
            float4 p1 = *(const float4*)&prw[1*PADL + kk4];
            float4 p2 = *(const float4*)&prw[2*PADL + kk4];
            float4 p3 = *(const float4*)&prw[3*PADL + kk4];
            #pragma unroll
            for (int j = 0; j < 6; j++) {
                float4 v = *(const float4*)&Vt[(lane + 32*j) * PADL + kk4];
                acc[0][j] += p0.x*v.x + p0.y*v.y + p0.z*v.z + p0.w*v.w;
                acc[1][j] += p1.x*v.x + p1.y*v.y + p1.z*v.z + p1.w*v.w;
                acc[2][j] += p2.x*v.x + p2.y*v.y + p2.z*v.z + p2.w*v.w;
                acc[3][j] += p3.x*v.x + p3.y*v.y + p3.z*v.z + p3.w*v.w;
            }
        }
        for (int t = 0; t < nq; t++) {
            size_t ro = (size_t)(b * LW + q0 + t) * Hc + h * HDc;
            #pragma unroll
            for (int j = 0; j < 6; j++) {
                float val = acc[t][j] * inv[t];
                split1(val, cth + ro + lane + 32*j, ctl + ro + lane + 32*j);
            }
        }
        __syncwarp();
    }
}

// ---------------- layernorm over H=768 per row + hi/lo ----------------------
__global__ void ln_kernel(const float* __restrict__ y,
                          const float* __restrict__ s,
                          const float* __restrict__ bi,
                          float* __restrict__ x,
                          __nv_bfloat16* __restrict__ xh,
                          __nv_bfloat16* __restrict__ xl) {
    int row = blockIdx.x;
    int tid = threadIdx.x;
    __shared__ float red[256];
    const float* yr = y + (size_t)row * Hc;
    float v0 = yr[tid], v1 = yr[tid+256], v2 = yr[tid+512];
    red[tid] = v0 + v1 + v2; __syncthreads();
    for (int o = 128; o > 0; o >>= 1) { if (tid < o) red[tid] += red[tid+o]; __syncthreads(); }
    float mean = red[0] * (1.f/768.f);
    __syncthreads();
    float d0 = v0-mean, d1 = v1-mean, d2 = v2-mean;
    red[tid] = d0*d0 + d1*d1 + d2*d2; __syncthreads();
    for (int o = 128; o > 0; o >>= 1) { if (tid < o) red[tid] += red[tid+o]; __syncthreads(); }
    float inv = rsqrtf(red[0] * (1.f/768.f) + 1e-5f);
    size_t ro = (size_t)row * Hc;
    float o0 = d0*inv*s[tid]     + bi[tid];
    float o1 = d1*inv*s[tid+256] + bi[tid+256];
    float o2 = d2*inv*s[tid+512] + bi[tid+512];
    x[ro+tid] = o0; x[ro+tid+256] = o1; x[ro+tid+512] = o2;
    split1(o0, xh + ro + tid,     xl + ro + tid);
    split1(o1, xh + ro + tid+256, xl + ro + tid+256);
    split1(o2, xh + ro + tid+512, xl + ro + tid+512);
}

// ---------------- classifier + pooled copy ----------------------------------
__global__ void cls_kernel(const float* __restrict__ x,
                           const float* __restrict__ cw,
                           const float* __restrict__ cb,
                           float* __restrict__ out) {
    int b = blockIdx.x;
    int tid = threadIdx.x;
    __shared__ float red[256];
    const float* row = x + (size_t)(b*LW) * Hc;
    out[Bc*NLABc + b*Hc + tid]     = row[tid];
    out[Bc*NLABc + b*Hc + tid+256] = row[tid+256];
    out[Bc*NLABc + b*Hc + tid+512] = row[tid+512];
    for (int lab = 0; lab < NLABc; lab++) {
        const float* wr = cw + lab*Hc;
        float s = row[tid]*wr[tid] + row[tid+256]*wr[tid+256] + row[tid+512]*wr[tid+512];
        red[tid] = s; __syncthreads();
        for (int o = 128; o > 0; o >>= 1) { if (tid < o) red[tid] += red[tid+o]; __syncthreads(); }
        if (tid == 0) out[b*NLABc + lab] = red[0] + cb[lab];
        __syncthreads();
    }
}

// ---------------- launch -----------------------------------------------------
extern "C" void kernel_launch(void* const* d_in, const int* in_sizes, int n_in,
                              void* d_out, int out_size) {
    (void)in_sizes; (void)n_in; (void)out_size;
    const float* hidden = (const float*)d_in[0];
    const int*   widx   = (const int*)  d_in[1];
    const void*  gmask  = d_in[2];
    const void*  wvin   = d_in[3];
    const float* qkv_w  = (const float*)d_in[4];
    const float* qkv_b  = (const float*)d_in[5];
    const float* out_w  = (const float*)d_in[6];
    const float* out_b  = (const float*)d_in[7];
    const float* ff1_w  = (const float*)d_in[8];
    const float* ff1_b  = (const float*)d_in[9];
    const float* ff2_w  = (const float*)d_in[10];
    const float* ff2_b  = (const float*)d_in[11];
    const float* ln1_s  = (const float*)d_in[12];
    const float* ln1_b  = (const float*)d_in[13];
    const float* ln2_s  = (const float*)d_in[14];
    const float* ln2_b  = (const float*)d_in[15];
    const float* cls_w  = (const float*)d_in[16];
    const float* cls_b  = (const float*)d_in[17];
    float* out = (float*)d_out;

    float *x, *qkv, *y, *wval;
    __nv_bfloat16 *wh, *wl, *xh, *xl, *cth, *ctl, *fh, *fl;
    cudaGetSymbolAddress((void**)&x,    g_x);
    cudaGetSymbolAddress((void**)&qkv,  g_qkv);
    cudaGetSymbolAddress((void**)&y,    g_y);
    cudaGetSymbolAddress((void**)&wval, g_wvalid);
    cudaGetSymbolAddress((void**)&wh,   g_wh);
    cudaGetSymbolAddress((void**)&wl,   g_wl);
    cudaGetSymbolAddress((void**)&xh,   g_xh);
    cudaGetSymbolAddress((void**)&xl,   g_xl);
    cudaGetSymbolAddress((void**)&cth,  g_cth);
    cudaGetSymbolAddress((void**)&ctl,  g_ctl);
    cudaGetSymbolAddress((void**)&fh,   g_fh);
    cudaGetSymbolAddress((void**)&fl,   g_fl);

    cudaFuncSetAttribute(hgemm_kernel<0>, cudaFuncAttributeMaxDynamicSharedMemorySize, (int)GEMM_SMEM);
    cudaFuncSetAttribute(hgemm_kernel<1>, cudaFuncAttributeMaxDynamicSharedMemorySize, (int)GEMM_SMEM);
    cudaFuncSetAttribute(hgemm_kernel<2>, cudaFuncAttributeMaxDynamicSharedMemorySize, (int)GEMM_SMEM);
    cudaFuncSetAttribute(attn_kernel,     cudaFuncAttributeMaxDynamicSharedMemorySize, (int)ATTN_SMEM);

    // weight conversion (once per launch, single merged launch)
    wconv_all_kernel<<<(WTOT/4 + 255)/256, 256>>>(qkv_w, out_w, ff1_w, ff2_w, wh, wl);

    detect_kernel<<<1, 256>>>((const unsigned int*)gmask, (const unsigned int*)wvin);
    build_kernel<<<dim3(LW, Bc), 256>>>(hidden, widx, gmask, wvin, x, xh, xl, wval);

    const int MB = (MROWS + 127) / 128;  // 33
    for (int l = 0; l < NLc; l++) {
        hgemm_kernel<0><<<dim3(H3/128, MB), 256, GEMM_SMEM>>>(
            xh, xl, wh + OFF_QKV + (size_t)l*H3*Hc, wl + OFF_QKV + (size_t)l*H3*Hc,
            qkv_b + (size_t)l*H3, nullptr, qkv, nullptr, nullptr,
            MROWS, H3, Hc);
        attn_kernel<<<dim3(NHc, Bc), 384, ATTN_SMEM>>>(qkv, wval, cth, ctl);
        hgemm_kernel<2><<<dim3(Hc/128, MB), 256, GEMM_SMEM>>>(
            cth, ctl, wh + OFF_OUT + (size_t)l*Hc*Hc, wl + OFF_OUT + (size_t)l*Hc*Hc,
            out_b + (size_t)l*Hc, x, y, nullptr, nullptr,
            MROWS, Hc, Hc);
        ln_kernel<<<MROWS, 256>>>(y, ln1_s + (size_t)l*Hc, ln1_b + (size_t)l*Hc, x, xh, xl);
        hgemm_kernel<1><<<dim3(FFc/128, MB), 256, GEMM_SMEM>>>(
            xh, xl, wh + OFF_FF1 + (size_t)l*FFc*Hc, wl + OFF_FF1 + (size_t)l*FFc*Hc,
            ff1_b + (size_t)l*FFc, nullptr, nullptr, fh, fl,
            MROWS, FFc, Hc);
        hgemm_kernel<2><<<dim3(Hc/128, MB), 256, GEMM_SMEM>>>(
            fh, fl, wh + OFF_FF2 + (size_t)l*Hc*FFc, wl + OFF_FF2 + (size_t)l*Hc*FFc,
            ff2_b + (size_t)l*Hc, x, y, nullptr, nullptr,
            MROWS, Hc, FFc);
        ln_kernel<<<MROWS, 256>>>(y, ln2_s + (size_t)l*Hc, ln2_b + (size_t)l*Hc, x, xh, xl);
    }
    cls_kernel<<<Bc, 256>>>(x, cls_w, cls_b, out);
}